// round 16
// baseline (speedup 1.0000x reference)
#include <cuda_runtime.h>
#include <cuda_fp16.h>
#include <cstdint>

constexpr int Hh = 8, DH = 64, INNER = 512, QLEN = 4096, KLEN = 308, CL = 77, CP = 80;
constexpr int QT = 64, NQT = QLEN / QT;     // 64 query tiles of 64 rows
constexpr int TPB = 128;                    // 4 warps
constexpr int LDH = 72;                     // halves per smem row (144B, ldmatrix conflict-free)

// device scratch
__device__ __half g_kh[2 * KLEN * INNER];
__device__ __half g_vh[2 * KLEN * INNER];
__device__ float  g_cs[4];                  // (128/sum)*log2(e)
__device__ unsigned char g_act[QLEN];

// smem: ONLY the K/V chunk buffer (Q fragments come straight from gmem)
constexpr int KV_BYTES = CP * LDH * 2;            // 11520
constexpr int OFF_K  = 0;
constexpr int OFF_V  = OFF_K + KV_BYTES;          // 11520
constexpr int SMEM_BYTES = OFF_V + KV_BYTES;      // 23040 -> 8 CTAs/SM (184KB)

__device__ __forceinline__ uint32_t h2u(float a, float b) {
    __half2 h = __floats2half2_rn(a, b);
    return *reinterpret_cast<uint32_t*>(&h);
}
// pack {lo=exp2(zlo), hi=exp2(zhi)} computed in fp16x2
__device__ __forceinline__ uint32_t cvtex2(float zlo, float zhi) {
    uint32_t t, d;
    asm("cvt.rn.satfinite.f16x2.f32 %0, %1, %2;" : "=r"(t) : "f"(zhi), "f"(zlo));
    asm("ex2.approx.f16x2 %0, %1;" : "=r"(d) : "r"(t));
    return d;
}
__device__ __forceinline__ void ldsm_x4(uint32_t* r, uint32_t addr) {
    asm volatile("ldmatrix.sync.aligned.m8n8.x4.shared.b16 {%0,%1,%2,%3}, [%4];"
                 : "=r"(r[0]), "=r"(r[1]), "=r"(r[2]), "=r"(r[3]) : "r"(addr));
}
__device__ __forceinline__ void ldsm_x4_t(uint32_t* r, uint32_t addr) {
    asm volatile("ldmatrix.sync.aligned.m8n8.x4.trans.shared.b16 {%0,%1,%2,%3}, [%4];"
                 : "=r"(r[0]), "=r"(r[1]), "=r"(r[2]), "=r"(r[3]) : "r"(addr));
}
__device__ __forceinline__ void ldsm_x2_t(uint32_t* r, uint32_t addr) {
    asm volatile("ldmatrix.sync.aligned.m8n8.x2.trans.shared.b16 {%0,%1}, [%2];"
                 : "=r"(r[0]), "=r"(r[1]) : "r"(addr));
}
__device__ __forceinline__ void mma16816(float* c, const uint32_t* a, uint32_t b0, uint32_t b1) {
    asm volatile("mma.sync.aligned.m16n8k16.row.col.f32.f16.f16.f32 "
                 "{%0,%1,%2,%3},{%4,%5,%6,%7},{%8,%9},{%0,%1,%2,%3};"
                 : "+f"(c[0]), "+f"(c[1]), "+f"(c[2]), "+f"(c[3])
                 : "r"(a[0]), "r"(a[1]), "r"(a[2]), "r"(a[3]), "r"(b0), "r"(b1));
}
__device__ __forceinline__ void cpa16(uint32_t s, const void* g) {
    asm volatile("cp.async.cg.shared.global [%0], [%1], 16;" :: "r"(s), "l"(g));
}

// ---------------------------------------------------------------------------
// prep: K,V -> fp16; region scales (x log2e); per-query activity bytes
// ---------------------------------------------------------------------------
__global__ void __launch_bounds__(256) prep_kernel(const float* __restrict__ k,
                                                   const float* __restrict__ v,
                                                   const float* __restrict__ dd)
{
    int blk = blockIdx.x, tid = threadIdx.x;
    if (blk < 308) {
        int idx = (blk * 256 + tid) * 4;               // over 2*308*512 floats
        float4 kf = *reinterpret_cast<const float4*>(k + idx);
        float4 vf = *reinterpret_cast<const float4*>(v + idx);
        *reinterpret_cast<uint2*>(reinterpret_cast<char*>(g_kh) + (size_t)idx * 2) =
            make_uint2(h2u(kf.x, kf.y), h2u(kf.z, kf.w));
        *reinterpret_cast<uint2*>(reinterpret_cast<char*>(g_vh) + (size_t)idx * 2) =
            make_uint2(h2u(vf.x, vf.y), h2u(vf.z, vf.w));
    } else if (blk == 308) {
        __shared__ float ws[4][8];
        int w = tid >> 5, l = tid & 31;
        #pragma unroll
        for (int r = 0; r < 4; r++) {
            float s = 0.f;
            #pragma unroll
            for (int i = 0; i < 4; i++) s += dd[r * 1024 + i * 256 + tid];
            #pragma unroll
            for (int o = 16; o > 0; o >>= 1) s += __shfl_xor_sync(0xffffffffu, s, o, 32);
            if (l == 0) ws[r][w] = s;
        }
        __syncthreads();
        if (tid < 4) {
            float s = 0.f;
            #pragma unroll
            for (int ww = 0; ww < 8; ww++) s += ws[tid][ww];
            g_cs[tid] = (128.f / s) * 1.4426950408889634f;
        }
    } else {
        int qg = (blk - 309) * 256 + tid;              // 16 blocks -> 4096
        int y = qg >> 6, x = qg & 63;
        unsigned a = 0;
        #pragma unroll
        for (int r = 0; r < 4; r++)
            if (dd[r * 1024 + (y >> 1) * 32 + (x >> 1)] > 0.5f) a |= 1u << r;
        g_act[qg] = (unsigned char)a;
    }
}

// ---------------------------------------------------------------------------
// main: fp16 mma.sync attention; Q fragments direct from gmem (no Q smem);
// fp16x2 exp; L as V col 64; 8 CTAs/SM -> single wave
// ---------------------------------------------------------------------------
__global__ void __launch_bounds__(TPB, 8)
ddca_kernel(const float* __restrict__ q, float* __restrict__ out)
{
    extern __shared__ char smc[];
    uint32_t sbase = (uint32_t)__cvta_generic_to_shared(smc);
    const uint32_t k_b = sbase + OFF_K;
    const uint32_t v_b = sbase + OFF_V;

    const int tid = threadIdx.x, w = tid >> 5, lane = tid & 31;
    const int gid = lane >> 2, tig = lane & 3;
    const int bid = blockIdx.x;
    const int qt = bid & 63, bh = bid >> 6, h = bh & 7, b = bh >> 3;

    const size_t kvbase = (size_t)b * KLEN * INNER + h * DH;

    // zero V/K pad rows 77..79 cols 0..71 (NaN safety; never restaged)
    if (tid < 108) {
        reinterpret_cast<uint32_t*>(smc + OFF_V + 77 * LDH * 2)[tid] = 0;
        reinterpret_cast<uint32_t*>(smc + OFF_K + 77 * LDH * 2)[tid] = 0;
    }
    // ones column: rows 0..79, col 64 = 1.0h, cols 65..71 = 0 (never restaged)
    if (tid < 80) {
        *reinterpret_cast<uint4*>(reinterpret_cast<half*>(smc + OFF_V) + tid * LDH + 64) =
            make_uint4(0x00003C00u, 0u, 0u, 0u);
    }

    // prologue: stage chunk 0 K/V (rows 0..76, cols 0..63)
    for (int i = tid; i < CL * 8; i += TPB) {
        int kk = i >> 3, d8 = (i & 7) * 8;
        size_t off = kvbase + (size_t)kk * INNER + d8;
        uint32_t so = (uint32_t)(kk * LDH + d8) * 2;
        cpa16(k_b + so, g_kh + off);
        cpa16(v_b + so, g_vh + off);
    }
    asm volatile("cp.async.commit_group;");

    // Q fragments DIRECT from gmem (m16n8k16 A layout; col pairs are even)
    uint32_t qf[4][4];
    {
        const float* q0 = q + ((size_t)(b * QLEN + qt * QT + 16 * w + gid)) * INNER + h * DH;
        const float* q8 = q0 + 8 * INNER;
        #pragma unroll
        for (int kt = 0; kt < 4; kt++) {
            int c0 = 16 * kt + 2 * tig, c1 = c0 + 8;
            float2 t;
            t = *reinterpret_cast<const float2*>(q0 + c0); qf[kt][0] = h2u(t.x, t.y);
            t = *reinterpret_cast<const float2*>(q8 + c0); qf[kt][1] = h2u(t.x, t.y);
            t = *reinterpret_cast<const float2*>(q0 + c1); qf[kt][2] = h2u(t.x, t.y);
            t = *reinterpret_cast<const float2*>(q8 + c1); qf[kt][3] = h2u(t.x, t.y);
        }
    }

    const unsigned a0 = g_act[qt * QT + 16 * w + gid];
    const unsigned a1 = g_act[qt * QT + 16 * w + gid + 8];

    const int krow  = (lane & 7) + ((lane >> 4) << 3);
    const int kcol0 = ((lane >> 3) & 1) << 3;

    float O[8][4];
    #pragma unroll
    for (int n = 0; n < 8; n++)
        #pragma unroll
        for (int e = 0; e < 4; e++) O[n][e] = 0.f;
    float LO[4] = {0.f, 0.f, 0.f, 0.f};          // L accumulator fragment (col 64)

    const bool bk0 = (tig <= 2), bk1 = (tig < 2);   // chunk col 72+2tig(+1) < 77

    #pragma unroll 1
    for (int c = 0; c < 4; c++) {
        asm volatile("cp.async.wait_group 0;");
        __syncthreads();                      // K/V chunk c visible

        const float c2 = g_cs[c];
        const float aR0 = ((a0 >> c) & 1) ? -8.f : -1e30f;
        const float aR1 = ((a1 >> c) & 1) ? -8.f : -1e30f;

        // ---- streamed per-16-key tile: S-tile -> exp(f16x2) -> O += P V ----
        #pragma unroll
        for (int np = 0; np < 5; np++) {
            float S0[4] = {0.f, 0.f, 0.f, 0.f};
            float S1[4] = {0.f, 0.f, 0.f, 0.f};
            #pragma unroll
            for (int kt = 0; kt < 4; kt++) {
                uint32_t bhf[4];
                ldsm_x4(bhf, k_b + (uint32_t)((16 * np + krow) * LDH + 16 * kt + kcol0) * 2);
                mma16816(S0, qf[kt], bhf[0], bhf[1]);
                mma16816(S1, qf[kt], bhf[2], bhf[3]);
            }

            // boundary adds only differ for the j1 tile at np==4
            const float b0e = (np < 4 || bk0) ? aR0 : -1e30f;
            const float b0o = (np < 4 || bk1) ? aR0 : -1e30f;
            const float b1e = (np < 4 || bk0) ? aR1 : -1e30f;
            const float b1o = (np < 4 || bk1) ? aR1 : -1e30f;
            uint32_t pA[4];
            pA[0] = cvtex2(fmaf(S0[0], c2, aR0), fmaf(S0[1], c2, aR0));
            pA[1] = cvtex2(fmaf(S0[2], c2, aR1), fmaf(S0[3], c2, aR1));
            pA[2] = cvtex2(fmaf(S1[0], c2, b0e), fmaf(S1[1], c2, b0o));
            pA[3] = cvtex2(fmaf(S1[2], c2, b1e), fmaf(S1[3], c2, b1o));

            #pragma unroll
            for (int dp = 0; dp < 4; dp++) {
                uint32_t vf[4];
                ldsm_x4_t(vf, v_b + (uint32_t)((16 * np + krow) * LDH + 16 * dp + kcol0) * 2);
                mma16816(O[2 * dp],     pA, vf[0], vf[2]);
                mma16816(O[2 * dp + 1], pA, vf[1], vf[3]);
            }
            // L column: V cols 64..71 (col 64 = ones)
            uint32_t vl[2];
            ldsm_x2_t(vl, v_b + (uint32_t)((16 * np + (lane & 15)) * LDH + 64) * 2);
            mma16816(LO, pA, vl[0], vl[1]);
        }

        // restage buffer with next chunk (all 4 warps done reading)
        if (c < 3) {
            __syncthreads();
            for (int i = tid; i < CL * 8; i += TPB) {
                int kk = i >> 3, d8 = (i & 7) * 8;
                size_t off = kvbase + (size_t)((c + 1) * CL + kk) * INNER + d8;
                uint32_t so = (uint32_t)(kk * LDH + d8) * 2;
                cpa16(k_b + so, g_kh + off);
                cpa16(v_b + so, g_vh + off);
            }
            asm volatile("cp.async.commit_group;");
        }
    }

    // ---- L lives in col 64 (tig==0 lanes); broadcast within each 4-lane group ----
    float Lg0 = __shfl_sync(0xffffffffu, LO[0], lane & ~3);
    float Lg1 = __shfl_sync(0xffffffffu, LO[2], lane & ~3);
    const float i0 = 1.f / Lg0, i1 = 1.f / Lg1;
    float* o0 = out + ((size_t)b * QLEN + (size_t)qt * QT + 16 * w + gid) * INNER + h * DH + 2 * tig;
    float* o1 = o0 + (size_t)8 * INNER;
    #pragma unroll
    for (int n = 0; n < 8; n++) {
        *reinterpret_cast<float2*>(o0 + 8 * n) = make_float2(O[n][0] * i0, O[n][1] * i0);
        *reinterpret_cast<float2*>(o1 + 8 * n) = make_float2(O[n][2] * i1, O[n][3] * i1);
    }
}

extern "C" void kernel_launch(void* const* d_in, const int* in_sizes, int n_in,
                              void* d_out, int out_size) {
    const float* q  = (const float*)d_in[0];
    const float* k  = (const float*)d_in[1];
    const float* v  = (const float*)d_in[2];
    const float* dd = (const float*)d_in[3];
    float* out = (float*)d_out;

    prep_kernel<<<325, 256>>>(k, v, dd);

    cudaFuncSetAttribute(ddca_kernel,
                         cudaFuncAttributeMaxDynamicSharedMemorySize, SMEM_BYTES);
    ddca_kernel<<<2 * Hh * NQT, TPB, SMEM_BYTES>>>(q, out);   // 1024 CTAs, 1 wave
}

// round 17
// speedup vs baseline: 1.2135x; 1.2135x over previous
#include <cuda_runtime.h>
#include <cuda_fp16.h>
#include <cstdint>

constexpr int Hh = 8, DH = 64, INNER = 512, QLEN = 4096, KLEN = 308, CL = 77, CP = 80;
constexpr int QT = 128, NQT = QLEN / QT;    // 32 query tiles of 128 rows
constexpr int TPB = 128;                    // 4 warps, each owns m32 (two m16 tiles)
constexpr int LDH = 72;                     // halves per smem row (144B, ldmatrix conflict-free)

// device scratch
__device__ __half g_kh[2 * KLEN * INNER];
__device__ __half g_vh[2 * KLEN * INNER];
__device__ float  g_cs[4];                  // (128/sum)*log2(e)
__device__ unsigned char g_act[QLEN];

// smem: Q (fp16, 128 rows) + single K buffer + single V buffer
constexpr int KV_BYTES = CP * LDH * 2;            // 11520
constexpr int OFF_QH = 0;
constexpr int OFF_K  = OFF_QH + QT * LDH * 2;     // 18432
constexpr int OFF_V  = OFF_K + KV_BYTES;          // 29952
constexpr int SMEM_BYTES = OFF_V + KV_BYTES;      // 41472 -> 4 CTAs/SM (reg-capped)

__device__ __forceinline__ uint32_t h2u(float a, float b) {
    __half2 h = __floats2half2_rn(a, b);
    return *reinterpret_cast<uint32_t*>(&h);
}
// pack {lo=exp2(zlo), hi=exp2(zhi)} computed in fp16x2
__device__ __forceinline__ uint32_t cvtex2(float zlo, float zhi) {
    uint32_t t, d;
    asm("cvt.rn.satfinite.f16x2.f32 %0, %1, %2;" : "=r"(t) : "f"(zhi), "f"(zlo));
    asm("ex2.approx.f16x2 %0, %1;" : "=r"(d) : "r"(t));
    return d;
}
__device__ __forceinline__ void ldsm_x4(uint32_t* r, uint32_t addr) {
    asm volatile("ldmatrix.sync.aligned.m8n8.x4.shared.b16 {%0,%1,%2,%3}, [%4];"
                 : "=r"(r[0]), "=r"(r[1]), "=r"(r[2]), "=r"(r[3]) : "r"(addr));
}
__device__ __forceinline__ void ldsm_x4_t(uint32_t* r, uint32_t addr) {
    asm volatile("ldmatrix.sync.aligned.m8n8.x4.trans.shared.b16 {%0,%1,%2,%3}, [%4];"
                 : "=r"(r[0]), "=r"(r[1]), "=r"(r[2]), "=r"(r[3]) : "r"(addr));
}
__device__ __forceinline__ void ldsm_x2_t(uint32_t* r, uint32_t addr) {
    asm volatile("ldmatrix.sync.aligned.m8n8.x2.trans.shared.b16 {%0,%1}, [%2];"
                 : "=r"(r[0]), "=r"(r[1]) : "r"(addr));
}
__device__ __forceinline__ void mma16816(float* c, const uint32_t* a, uint32_t b0, uint32_t b1) {
    asm volatile("mma.sync.aligned.m16n8k16.row.col.f32.f16.f16.f32 "
                 "{%0,%1,%2,%3},{%4,%5,%6,%7},{%8,%9},{%0,%1,%2,%3};"
                 : "+f"(c[0]), "+f"(c[1]), "+f"(c[2]), "+f"(c[3])
                 : "r"(a[0]), "r"(a[1]), "r"(a[2]), "r"(a[3]), "r"(b0), "r"(b1));
}
__device__ __forceinline__ void cpa16(uint32_t s, const void* g) {
    asm volatile("cp.async.cg.shared.global [%0], [%1], 16;" :: "r"(s), "l"(g));
}

// ---------------------------------------------------------------------------
// prep: K,V -> fp16; region scales (x log2e); per-query activity bytes
// ---------------------------------------------------------------------------
__global__ void __launch_bounds__(256) prep_kernel(const float* __restrict__ k,
                                                   const float* __restrict__ v,
                                                   const float* __restrict__ dd)
{
    int blk = blockIdx.x, tid = threadIdx.x;
    if (blk < 308) {
        int idx = (blk * 256 + tid) * 4;               // over 2*308*512 floats
        float4 kf = *reinterpret_cast<const float4*>(k + idx);
        float4 vf = *reinterpret_cast<const float4*>(v + idx);
        *reinterpret_cast<uint2*>(reinterpret_cast<char*>(g_kh) + (size_t)idx * 2) =
            make_uint2(h2u(kf.x, kf.y), h2u(kf.z, kf.w));
        *reinterpret_cast<uint2*>(reinterpret_cast<char*>(g_vh) + (size_t)idx * 2) =
            make_uint2(h2u(vf.x, vf.y), h2u(vf.z, vf.w));
    } else if (blk == 308) {
        __shared__ float ws[4][8];
        int w = tid >> 5, l = tid & 31;
        #pragma unroll
        for (int r = 0; r < 4; r++) {
            float s = 0.f;
            #pragma unroll
            for (int i = 0; i < 4; i++) s += dd[r * 1024 + i * 256 + tid];
            #pragma unroll
            for (int o = 16; o > 0; o >>= 1) s += __shfl_xor_sync(0xffffffffu, s, o, 32);
            if (l == 0) ws[r][w] = s;
        }
        __syncthreads();
        if (tid < 4) {
            float s = 0.f;
            #pragma unroll
            for (int ww = 0; ww < 8; ww++) s += ws[tid][ww];
            g_cs[tid] = (128.f / s) * 1.4426950408889634f;
        }
    } else {
        int qg = (blk - 309) * 256 + tid;              // 16 blocks -> 4096
        int y = qg >> 6, x = qg & 63;
        unsigned a = 0;
        #pragma unroll
        for (int r = 0; r < 4; r++)
            if (dd[r * 1024 + (y >> 1) * 32 + (x >> 1)] > 0.5f) a |= 1u << r;
        g_act[qg] = (unsigned char)a;
    }
}

// ---------------------------------------------------------------------------
// main: fp16 mma.sync attention; m32 warp tile (two m16 row-tiles share all
// K/V fragments); fp16x2 exp; L as V col 64
// ---------------------------------------------------------------------------
__global__ void __launch_bounds__(TPB, 4)
ddca_kernel(const float* __restrict__ q, float* __restrict__ out)
{
    extern __shared__ char smc[];
    half* Qh = (half*)(smc + OFF_QH);
    uint32_t sbase = (uint32_t)__cvta_generic_to_shared(smc);
    const uint32_t qh_b = sbase + OFF_QH;
    const uint32_t k_b  = sbase + OFF_K;
    const uint32_t v_b  = sbase + OFF_V;

    const int tid = threadIdx.x, w = tid >> 5, lane = tid & 31;
    const int gid = lane >> 2, tig = lane & 3;
    const int bid = blockIdx.x;
    const int qt = bid & 31, bh = bid >> 5, h = bh & 7, b = bh >> 3;

    const float* qp = q + ((size_t)b * QLEN + (size_t)qt * QT) * INNER + h * DH;
    const size_t kvbase = (size_t)b * KLEN * INNER + h * DH;

    // zero V/K pad rows 77..79 cols 0..71 (NaN safety; never restaged)
    if (tid < 108) {
        reinterpret_cast<uint32_t*>(smc + OFF_V + 77 * LDH * 2)[tid] = 0;
        reinterpret_cast<uint32_t*>(smc + OFF_K + 77 * LDH * 2)[tid] = 0;
    }
    // ones column: rows 0..79, col 64 = 1.0h, cols 65..71 = 0 (never restaged)
    if (tid < 80) {
        *reinterpret_cast<uint4*>(reinterpret_cast<half*>(smc + OFF_V) + tid * LDH + 64) =
            make_uint4(0x00003C00u, 0u, 0u, 0u);
    }

    // prologue: stage chunk 0 K/V (rows 0..76, cols 0..63)
    for (int i = tid; i < CL * 8; i += TPB) {
        int kk = i >> 3, d8 = (i & 7) * 8;
        size_t off = kvbase + (size_t)kk * INNER + d8;
        uint32_t so = (uint32_t)(kk * LDH + d8) * 2;
        cpa16(k_b + so, g_kh + off);
        cpa16(v_b + so, g_vh + off);
    }
    asm volatile("cp.async.commit_group;");

    // stage Q (fp16 rounded): 128 rows x 16 groups = 2048 / 128 thr = 16 iters
    #pragma unroll
    for (int it = 0; it < 16; it++) {
        int i4 = tid + it * TPB;
        int row = i4 >> 4, dq = (i4 & 15) * 4;
        float4 t = *reinterpret_cast<const float4*>(qp + (size_t)row * INNER + dq);
        *reinterpret_cast<uint2*>(Qh + row * LDH + dq) =
            make_uint2(h2u(t.x, t.y), h2u(t.z, t.w));
    }

    // activity bytes for the 4 rows this thread's fragments touch
    const unsigned aA0 = g_act[qt * QT + 32 * w + gid];
    const unsigned aA1 = g_act[qt * QT + 32 * w + gid + 8];
    const unsigned aB0 = g_act[qt * QT + 32 * w + gid + 16];
    const unsigned aB1 = g_act[qt * QT + 32 * w + gid + 24];

    const int qrowA = 32 * w + (lane & 15);         // tile A rows
    const int qcol0 = (lane >> 4) << 3;
    const int krow  = (lane & 7) + ((lane >> 4) << 3);
    const int kcol0 = ((lane >> 3) & 1) << 3;

    float OA[8][4], OB[8][4];
    #pragma unroll
    for (int n = 0; n < 8; n++)
        #pragma unroll
        for (int e = 0; e < 4; e++) { OA[n][e] = 0.f; OB[n][e] = 0.f; }
    float LA[4] = {0.f, 0.f, 0.f, 0.f};
    float LB[4] = {0.f, 0.f, 0.f, 0.f};
    uint32_t qfA[4][4], qfB[4][4];
    bool qload = false;

    const bool bk0 = (tig <= 2), bk1 = (tig < 2);   // chunk col 72+2tig(+1) < 77

    #pragma unroll 1
    for (int c = 0; c < 4; c++) {
        asm volatile("cp.async.wait_group 0;");
        __syncthreads();                      // K/V chunk c (and Q on c=0) visible

        if (!qload) {                         // both tiles' Q fragments, persistent
            #pragma unroll
            for (int kt = 0; kt < 4; kt++) {
                ldsm_x4(qfA[kt], qh_b + (uint32_t)(qrowA * LDH + 16 * kt + qcol0) * 2);
                ldsm_x4(qfB[kt], qh_b + (uint32_t)((qrowA + 16) * LDH + 16 * kt + qcol0) * 2);
            }
            qload = true;
        }

        const float c2 = g_cs[c];
        const float rA0 = ((aA0 >> c) & 1) ? -8.f : -1e30f;
        const float rA1 = ((aA1 >> c) & 1) ? -8.f : -1e30f;
        const float rB0 = ((aB0 >> c) & 1) ? -8.f : -1e30f;
        const float rB1 = ((aB1 >> c) & 1) ? -8.f : -1e30f;

        // ---- streamed per-16-key tile: S (A+B) -> exp -> O += P V (A+B) ----
        #pragma unroll
        for (int np = 0; np < 5; np++) {
            float SA0[4] = {0.f,0.f,0.f,0.f}, SA1[4] = {0.f,0.f,0.f,0.f};
            float SB0[4] = {0.f,0.f,0.f,0.f}, SB1[4] = {0.f,0.f,0.f,0.f};
            #pragma unroll
            for (int kt = 0; kt < 4; kt++) {
                uint32_t bhf[4];
                ldsm_x4(bhf, k_b + (uint32_t)((16 * np + krow) * LDH + 16 * kt + kcol0) * 2);
                mma16816(SA0, qfA[kt], bhf[0], bhf[1]);
                mma16816(SA1, qfA[kt], bhf[2], bhf[3]);
                mma16816(SB0, qfB[kt], bhf[0], bhf[1]);
                mma16816(SB1, qfB[kt], bhf[2], bhf[3]);
            }

            const bool be = (np < 4 || bk0), bo = (np < 4 || bk1);
            uint32_t pA[4], pB[4];
            {
                const float b0e = be ? rA0 : -1e30f, b0o = bo ? rA0 : -1e30f;
                const float b1e = be ? rA1 : -1e30f, b1o = bo ? rA1 : -1e30f;
                pA[0] = cvtex2(fmaf(SA0[0], c2, rA0), fmaf(SA0[1], c2, rA0));
                pA[1] = cvtex2(fmaf(SA0[2], c2, rA1), fmaf(SA0[3], c2, rA1));
                pA[2] = cvtex2(fmaf(SA1[0], c2, b0e), fmaf(SA1[1], c2, b0o));
                pA[3] = cvtex2(fmaf(SA1[2], c2, b1e), fmaf(SA1[3], c2, b1o));
            }
            {
                const float b0e = be ? rB0 : -1e30f, b0o = bo ? rB0 : -1e30f;
                const float b1e = be ? rB1 : -1e30f, b1o = bo ? rB1 : -1e30f;
                pB[0] = cvtex2(fmaf(SB0[0], c2, rB0), fmaf(SB0[1], c2, rB0));
                pB[1] = cvtex2(fmaf(SB0[2], c2, rB1), fmaf(SB0[3], c2, rB1));
                pB[2] = cvtex2(fmaf(SB1[0], c2, b0e), fmaf(SB1[1], c2, b0o));
                pB[3] = cvtex2(fmaf(SB1[2], c2, b1e), fmaf(SB1[3], c2, b1o));
            }

            #pragma unroll
            for (int dp = 0; dp < 4; dp++) {
                uint32_t vf[4];
                ldsm_x4_t(vf, v_b + (uint32_t)((16 * np + krow) * LDH + 16 * dp + kcol0) * 2);
                mma16816(OA[2 * dp],     pA, vf[0], vf[2]);
                mma16816(OA[2 * dp + 1], pA, vf[1], vf[3]);
                mma16816(OB[2 * dp],     pB, vf[0], vf[2]);
                mma16816(OB[2 * dp + 1], pB, vf[1], vf[3]);
            }
            // L column: V cols 64..71 (col 64 = ones), shared by both tiles
            uint32_t vl[2];
            ldsm_x2_t(vl, v_b + (uint32_t)((16 * np + (lane & 15)) * LDH + 64) * 2);
            mma16816(LA, pA, vl[0], vl[1]);
            mma16816(LB, pB, vl[0], vl[1]);
        }

        // restage buffer with next chunk (all 4 warps done reading)
        if (c < 3) {
            __syncthreads();
            for (int i = tid; i < CL * 8; i += TPB) {
                int kk = i >> 3, d8 = (i & 7) * 8;
                size_t off = kvbase + (size_t)((c + 1) * CL + kk) * INNER + d8;
                uint32_t so = (uint32_t)(kk * LDH + d8) * 2;
                cpa16(k_b + so, g_kh + off);
                cpa16(v_b + so, g_vh + off);
            }
            asm volatile("cp.async.commit_group;");
        }
    }

    // ---- L in col 64 (tig==0 lanes); broadcast within each 4-lane group ----
    float LgA0 = __shfl_sync(0xffffffffu, LA[0], lane & ~3);
    float LgA1 = __shfl_sync(0xffffffffu, LA[2], lane & ~3);
    float LgB0 = __shfl_sync(0xffffffffu, LB[0], lane & ~3);
    float LgB1 = __shfl_sync(0xffffffffu, LB[2], lane & ~3);
    const float iA0 = 1.f / LgA0, iA1 = 1.f / LgA1;
    const float iB0 = 1.f / LgB0, iB1 = 1.f / LgB1;
    float* oA = out + ((size_t)b * QLEN + (size_t)qt * QT + 32 * w + gid) * INNER + h * DH + 2 * tig;
    float* oB = oA + (size_t)16 * INNER;
    #pragma unroll
    for (int n = 0; n < 8; n++) {
        *reinterpret_cast<float2*>(oA + 8 * n) = make_float2(OA[n][0] * iA0, OA[n][1] * iA0);
        *reinterpret_cast<float2*>(oA + (size_t)8 * INNER + 8 * n) =
            make_float2(OA[n][2] * iA1, OA[n][3] * iA1);
        *reinterpret_cast<float2*>(oB + 8 * n) = make_float2(OB[n][0] * iB0, OB[n][1] * iB0);
        *reinterpret_cast<float2*>(oB + (size_t)8 * INNER + 8 * n) =
            make_float2(OB[n][2] * iB1, OB[n][3] * iB1);
    }
}

extern "C" void kernel_launch(void* const* d_in, const int* in_sizes, int n_in,
                              void* d_out, int out_size) {
    const float* q  = (const float*)d_in[0];
    const float* k  = (const float*)d_in[1];
    const float* v  = (const float*)d_in[2];
    const float* dd = (const float*)d_in[3];
    float* out = (float*)d_out;

    prep_kernel<<<325, 256>>>(k, v, dd);

    cudaFuncSetAttribute(ddca_kernel,
                         cudaFuncAttributeMaxDynamicSharedMemorySize, SMEM_BYTES);
    ddca_kernel<<<2 * Hh * NQT, TPB, SMEM_BYTES>>>(q, out);   // 512 CTAs
}